// round 15
// baseline (speedup 1.0000x reference)
#include <cuda_runtime.h>

// Problem constants
#define HW2        65536      // 256*256 pixels
#define N_PIX      65536
#define N_Q        16384      // pixel quads (float4 granularity)
#define BATCH      64
#define COV_Q      128        // quads per covar block
#define NBLK_COV   128        // covar blocks
#define NBLK_ZERO  20         // dedicated zero-writer blocks (one wave: 128+20 <= 148 SMs)
#define DIFF_OFF   ((size_t)BATCH * 6 * N_Q)   // 6291456 float4
#define ZERO_TOTAL (3 * BATCH * N_Q)           // 3145728 float4 of diffusion_x zeros

// Scratch (allocation-free rule: __device__ globals)
__device__ float g_G[6 * N_PIX];       // covariance planes g00,g01,g02,g11,g12,g22
__device__ float g_mats[18 * N_PIX];   // A(9), 8L(6), d(3) — plane-major
__device__ float g_partial[NBLK_COV];  // per-block trace partial sums

// ---- float4 helpers --------------------------------------------------------
__device__ __forceinline__ float4 f4mul(float4 a, float4 b) {
    return make_float4(a.x * b.x, a.y * b.y, a.z * b.z, a.w * b.w);
}
__device__ __forceinline__ float4 f4fma(float4 a, float4 b, float4 c) {
    return make_float4(fmaf(a.x, b.x, c.x), fmaf(a.y, b.y, c.y),
                       fmaf(a.z, b.z, c.z), fmaf(a.w, b.w, c.w));
}
__device__ __forceinline__ float4 f4neg(float4 a) {
    return make_float4(-a.x, -a.y, -a.z, -a.w);
}
__device__ __forceinline__ float4 f4add(float4 a, float4 b) {
    return make_float4(a.x + b.x, a.y + b.y, a.z + b.z, a.w + b.w);
}
__device__ __forceinline__ float4 f4scale(float4 a, float s) {
    return make_float4(a.x * s, a.y * s, a.z * s, a.w * s);
}

// ---------------------------------------------------------------------------
// Kernel 1: block-specialized covariance + diffusion_x zero-fill.
// Blocks [0,128): per-pixel covariance (latency-floor-bound reads, ~4.1 TB/s,
//   leaves write BW idle). Blocks [128,148): pure zero-writers on OTHER SMs,
//   streaming 50 MB of diffusion_x zeros into the idle write bandwidth.
// __stcs = evict-first so zeros write back to DRAM during this window,
// not during the BW-bound apply kernel (the R13 failure mode).
// ---------------------------------------------------------------------------
__global__ __launch_bounds__(1024, 1) void k_covar(const float4* __restrict__ s4,
                                                   float4* __restrict__ out4) {
    const int tid = threadIdx.x;

    // ---- zero-writer blocks -------------------------------------------------
    if (blockIdx.x >= NBLK_COV) {
        const float4 zero = make_float4(0.f, 0.f, 0.f, 0.f);
        const int zb = blockIdx.x - NBLK_COV;
        for (size_t z = (size_t)zb * 1024 + tid; z < ZERO_TOTAL;
             z += (size_t)NBLK_ZERO * 1024) {
            const size_t b   = z / (3 * N_Q);
            const size_t rem = z - b * (3 * N_Q);
            __stcs(out4 + DIFF_OFF + b * (6 * N_Q) + rem, zero);
        }
        return;
    }

    // ---- covariance blocks (identical to R12 best) --------------------------
    const int ql  = tid & (COV_Q - 1);        // quad-local 0..127
    const int sp  = tid >> 7;                 // split 0..7 (warp-uniform)
    const int q   = blockIdx.x * COV_Q + ql;  // global quad

    float4 a0 = make_float4(0.f, 0.f, 0.f, 0.f);
    float4 a1 = a0, a2 = a0, a3 = a0, a4 = a0, a5 = a0;

#pragma unroll 2
    for (int i = 0; i < 8; ++i) {
        const int b = sp * 8 + i;
        const float4* base = s4 + (size_t)b * (3 * N_Q) + q;
        const float4 s0 = __ldcs(base);
        const float4 s1 = __ldcs(base + N_Q);
        const float4 s2 = __ldcs(base + 2 * N_Q);
        a0 = f4fma(s0, s0, a0); a1 = f4fma(s0, s1, a1); a2 = f4fma(s0, s2, a2);
        a3 = f4fma(s1, s1, a3); a4 = f4fma(s1, s2, a4); a5 = f4fma(s2, s2, a5);
    }

    // staged reduction: 8 -> 4 -> 2 -> 1 splits, 48 KB smem
    __shared__ float4 sh[4][6][COV_Q];

    if (sp >= 4) {
        sh[sp - 4][0][ql] = a0; sh[sp - 4][1][ql] = a1; sh[sp - 4][2][ql] = a2;
        sh[sp - 4][3][ql] = a3; sh[sp - 4][4][ql] = a4; sh[sp - 4][5][ql] = a5;
    }
    __syncthreads();
    if (sp < 4) {
        a0 = f4add(a0, sh[sp][0][ql]); a1 = f4add(a1, sh[sp][1][ql]);
        a2 = f4add(a2, sh[sp][2][ql]); a3 = f4add(a3, sh[sp][3][ql]);
        a4 = f4add(a4, sh[sp][4][ql]); a5 = f4add(a5, sh[sp][5][ql]);
    }
    __syncthreads();
    if (sp == 2 || sp == 3) {
        sh[sp - 2][0][ql] = a0; sh[sp - 2][1][ql] = a1; sh[sp - 2][2][ql] = a2;
        sh[sp - 2][3][ql] = a3; sh[sp - 2][4][ql] = a4; sh[sp - 2][5][ql] = a5;
    }
    __syncthreads();
    if (sp < 2) {
        a0 = f4add(a0, sh[sp][0][ql]); a1 = f4add(a1, sh[sp][1][ql]);
        a2 = f4add(a2, sh[sp][2][ql]); a3 = f4add(a3, sh[sp][3][ql]);
        a4 = f4add(a4, sh[sp][4][ql]); a5 = f4add(a5, sh[sp][5][ql]);
    }
    __syncthreads();
    if (sp == 1) {
        sh[0][0][ql] = a0; sh[0][1][ql] = a1; sh[0][2][ql] = a2;
        sh[0][3][ql] = a3; sh[0][4][ql] = a4; sh[0][5][ql] = a5;
    }
    __syncthreads();

    float tr = 0.f;
    if (sp == 0) {
        const float ib = 1.0f / 64.0f;
        a0 = f4scale(f4add(a0, sh[0][0][ql]), ib);
        a1 = f4scale(f4add(a1, sh[0][1][ql]), ib);
        a2 = f4scale(f4add(a2, sh[0][2][ql]), ib);
        a3 = f4scale(f4add(a3, sh[0][3][ql]), ib);
        a4 = f4scale(f4add(a4, sh[0][4][ql]), ib);
        a5 = f4scale(f4add(a5, sh[0][5][ql]), ib);

        float4* g4 = (float4*)g_G;
        g4[0 * N_Q + q] = a0; g4[1 * N_Q + q] = a1; g4[2 * N_Q + q] = a2;
        g4[3 * N_Q + q] = a3; g4[4 * N_Q + q] = a4; g4[5 * N_Q + q] = a5;

        const float4 td = f4add(f4add(a0, a3), a5);
        tr = td.x + td.y + td.z + td.w;
#pragma unroll
        for (int o = 16; o > 0; o >>= 1)
            tr += __shfl_down_sync(0xffffffffu, tr, o);
    }

    __shared__ float shr[4];
    if (sp == 0 && (tid & 31) == 0) shr[tid >> 5] = tr;
    __syncthreads();
    if (tid == 0)
        g_partial[blockIdx.x] = shr[0] + shr[1] + shr[2] + shr[3];
}

// ---------------------------------------------------------------------------
// Kernel 2: per-pixel matrix prep (fp32).
//   G = alpha*G/norm + (1-alpha)*0.25*I
//   A = 8*L*Ginv ; 8L ; d = sqrt(1.28)*rowsum(L)
//   (C = 0.64*G*Ginv == 0.64*I at fp32 rounding — folded into k_apply.)
// ---------------------------------------------------------------------------
__global__ __launch_bounds__(256) void k_prep(const float* __restrict__ t) {
    // reduce 128 trace partials redundantly per block
    __shared__ float sh_sum;
    {
        float v = (threadIdx.x < NBLK_COV) ? g_partial[threadIdx.x] : 0.f;
#pragma unroll
        for (int o = 16; o > 0; o >>= 1)
            v += __shfl_down_sync(0xffffffffu, v, o);
        __shared__ float sh[8];
        const int lane = threadIdx.x & 31;
        const int w    = threadIdx.x >> 5;
        if (lane == 0) sh[w] = v;
        __syncthreads();
        if (threadIdx.x == 0) {
            float acc = 0.f;
#pragma unroll
            for (int i = 0; i < 8; ++i) acc += sh[i];
            sh_sum = acc;
        }
        __syncthreads();
    }

    const int p = blockIdx.x * blockDim.x + threadIdx.x;
    const float t0 = __ldg(t);
    const float diag_mean = sh_sum / (65536.0f * 3.0f);
    const float norm  = (t0 == 1.0f) ? diag_mean * 4.0f : 1.0f;
    const float alpha = 0.5f * __expf(-4.5f * (1.0f - t0));
    const float sa = alpha / norm;
    const float diag_add = (1.0f - alpha) * 0.25f;

    const float a00 = g_G[0 * N_PIX + p] * sa + diag_add;
    const float a01 = g_G[1 * N_PIX + p] * sa;
    const float a02 = g_G[2 * N_PIX + p] * sa;
    const float a11 = g_G[3 * N_PIX + p] * sa + diag_add;
    const float a12 = g_G[4 * N_PIX + p] * sa;
    const float a22 = g_G[5 * N_PIX + p] * sa + diag_add;

    // adjugate inverse (fp32)
    const float c00 = a11 * a22 - a12 * a12;
    const float c01 = a02 * a12 - a01 * a22;
    const float c02 = a01 * a12 - a02 * a11;
    const float det = a00 * c00 + a01 * c01 + a02 * c02;
    const float id  = 1.0f / det;
    const float i00 = c00 * id;
    const float i01 = c01 * id;
    const float i02 = c02 * id;
    const float i11 = (a00 * a22 - a02 * a02) * id;
    const float i12 = (a01 * a02 - a00 * a12) * id;
    const float i22 = (a00 * a11 - a01 * a01) * id;

    // Cholesky (fp32)
    const float l00 = sqrtf(a00);
    const float il00 = 1.0f / l00;
    const float l10 = a01 * il00;
    const float l20 = a02 * il00;
    const float l11 = sqrtf(a11 - l10 * l10);
    const float l21 = (a12 - l20 * l10) / l11;
    const float l22 = sqrtf(a22 - l20 * l20 - l21 * l21);

    // A = 8 * L * Ginv
    const float A00 = 8.0f * (l00 * i00);
    const float A01 = 8.0f * (l00 * i01);
    const float A02 = 8.0f * (l00 * i02);
    const float A10 = 8.0f * (l10 * i00 + l11 * i01);
    const float A11 = 8.0f * (l10 * i01 + l11 * i11);
    const float A12 = 8.0f * (l10 * i02 + l11 * i12);
    const float A20 = 8.0f * (l20 * i00 + l21 * i01 + l22 * i02);
    const float A21 = 8.0f * (l20 * i01 + l21 * i11 + l22 * i12);
    const float A22 = 8.0f * (l20 * i02 + l21 * i12 + l22 * i22);

    const float bg = 1.1313708498984762f;  // sqrt(2*8*0.08)

    float* m = g_mats;
    m[ 0 * N_PIX + p] = A00; m[ 1 * N_PIX + p] = A01; m[ 2 * N_PIX + p] = A02;
    m[ 3 * N_PIX + p] = A10; m[ 4 * N_PIX + p] = A11; m[ 5 * N_PIX + p] = A12;
    m[ 6 * N_PIX + p] = A20; m[ 7 * N_PIX + p] = A21; m[ 8 * N_PIX + p] = A22;
    m[ 9 * N_PIX + p] = 8.0f * l00;
    m[10 * N_PIX + p] = 8.0f * l10;
    m[11 * N_PIX + p] = 8.0f * l11;
    m[12 * N_PIX + p] = 8.0f * l20;
    m[13 * N_PIX + p] = 8.0f * l21;
    m[14 * N_PIX + p] = 8.0f * l22;
    m[15 * N_PIX + p] = bg * l00;
    m[16 * N_PIX + p] = bg * (l10 + l11);
    m[17 * N_PIX + p] = bg * (l20 + l21 + l22);
}

// ---------------------------------------------------------------------------
// Kernel 3: streaming apply, float4 pixel-quads, 4 batches per thread.
//   drift_x = A r ; drift_r = -(8L) x - 0.64 r ; diffusion_r = d
// diffusion_x zeros written concurrently with covar — 50 MB less here.
// ---------------------------------------------------------------------------
__global__ __launch_bounds__(256) void k_apply(const float4* __restrict__ u4,
                                               float4* __restrict__ out4) {
    const int idx = blockIdx.x * blockDim.x + threadIdx.x;  // 0..262143
    const int q   = idx & (N_Q - 1);
    const int bq  = idx >> 14;  // 0..15

    const float4* m4 = (const float4*)g_mats;
    const float4 A00 = __ldg(m4 +  0 * N_Q + q), A01 = __ldg(m4 +  1 * N_Q + q), A02 = __ldg(m4 +  2 * N_Q + q);
    const float4 A10 = __ldg(m4 +  3 * N_Q + q), A11 = __ldg(m4 +  4 * N_Q + q), A12 = __ldg(m4 +  5 * N_Q + q);
    const float4 A20 = __ldg(m4 +  6 * N_Q + q), A21 = __ldg(m4 +  7 * N_Q + q), A22 = __ldg(m4 +  8 * N_Q + q);
    const float4 L00 = __ldg(m4 +  9 * N_Q + q);
    const float4 L10 = __ldg(m4 + 10 * N_Q + q), L11 = __ldg(m4 + 11 * N_Q + q);
    const float4 L20 = __ldg(m4 + 12 * N_Q + q), L21 = __ldg(m4 + 13 * N_Q + q), L22 = __ldg(m4 + 14 * N_Q + q);
    const float4 D0  = __ldg(m4 + 15 * N_Q + q), D1 = __ldg(m4 + 16 * N_Q + q), D2 = __ldg(m4 + 17 * N_Q + q);

    const float cg = 0.64f;  // 0.64 * G * Ginv == 0.64 * I (fp32 rounding level)

#pragma unroll
    for (int i = 0; i < 4; ++i) {
        const int b = bq * 4 + i;
        const float4* ub = u4 + (size_t)b * (6 * N_Q) + q;
        const float4 x0 = __ldcs(ub);
        const float4 x1 = __ldcs(ub + N_Q);
        const float4 x2 = __ldcs(ub + 2 * N_Q);
        const float4 r0 = __ldcs(ub + 3 * N_Q);
        const float4 r1 = __ldcs(ub + 4 * N_Q);
        const float4 r2 = __ldcs(ub + 5 * N_Q);

        // drift_x = A r
        const float4 dx0 = f4fma(A02, r2, f4fma(A01, r1, f4mul(A00, r0)));
        const float4 dx1 = f4fma(A12, r2, f4fma(A11, r1, f4mul(A10, r0)));
        const float4 dx2 = f4fma(A22, r2, f4fma(A21, r1, f4mul(A20, r0)));
        // drift_r = -( (8L) x + 0.64 r )
        const float4 dr0 = f4neg(f4fma(L00, x0, f4scale(r0, cg)));
        const float4 dr1 = f4neg(f4fma(L11, x1, f4fma(L10, x0, f4scale(r1, cg))));
        const float4 dr2 = f4neg(f4fma(L22, x2, f4fma(L21, x1, f4fma(L20, x0, f4scale(r2, cg)))));

        float4* ob = out4 + (size_t)b * (6 * N_Q) + q;
        __stcs(ob + 0 * N_Q, dx0);
        __stcs(ob + 1 * N_Q, dx1);
        __stcs(ob + 2 * N_Q, dx2);
        __stcs(ob + 3 * N_Q, dr0);
        __stcs(ob + 4 * N_Q, dr1);
        __stcs(ob + 5 * N_Q, dr2);

        float4* db = ob + DIFF_OFF;
        __stcs(db + 3 * N_Q, D0);
        __stcs(db + 4 * N_Q, D1);
        __stcs(db + 5 * N_Q, D2);
    }
}

// ---------------------------------------------------------------------------
extern "C" void kernel_launch(void* const* d_in, const int* in_sizes, int n_in,
                              void* d_out, int out_size) {
    const float4* u4 = (const float4*)d_in[0];   // [64, 6, 256, 256]
    const float4* s4 = (const float4*)d_in[1];   // [64, 3, 256, 256]
    const float*  t  = (const float*)d_in[2];    // [64]
    float4* out4 = (float4*)d_out;               // drift + diffusion

    k_covar<<<NBLK_COV + NBLK_ZERO, 1024>>>(s4, out4);
    k_prep<<<N_PIX / 256, 256>>>(t);
    k_apply<<<(N_Q * 16) / 256, 256>>>(u4, out4);
}

// round 16
// speedup vs baseline: 1.4487x; 1.4487x over previous
#include <cuda_runtime.h>

// Problem constants
#define HW2        65536      // 256*256 pixels
#define N_PIX      65536
#define N_Q        16384      // pixel quads (float4 granularity)
#define BATCH      64
#define COV_Q      128        // quads per covar block
#define NBLK_COV   128        // 16384 / 128

// Scratch (allocation-free rule: __device__ globals)
__device__ float g_G[6 * N_PIX];       // covariance planes g00,g01,g02,g11,g12,g22
__device__ float g_mats[18 * N_PIX];   // A(9), 8L(6), d(3) — plane-major
__device__ float g_partial[NBLK_COV];  // per-block trace partial sums

// ---- float4 helpers --------------------------------------------------------
__device__ __forceinline__ float4 f4mul(float4 a, float4 b) {
    return make_float4(a.x * b.x, a.y * b.y, a.z * b.z, a.w * b.w);
}
__device__ __forceinline__ float4 f4fma(float4 a, float4 b, float4 c) {
    return make_float4(fmaf(a.x, b.x, c.x), fmaf(a.y, b.y, c.y),
                       fmaf(a.z, b.z, c.z), fmaf(a.w, b.w, c.w));
}
__device__ __forceinline__ float4 f4neg(float4 a) {
    return make_float4(-a.x, -a.y, -a.z, -a.w);
}
__device__ __forceinline__ float4 f4add(float4 a, float4 b) {
    return make_float4(a.x + b.x, a.y + b.y, a.z + b.z, a.w + b.w);
}
__device__ __forceinline__ float4 f4scale(float4 a, float s) {
    return make_float4(a.x * s, a.y * s, a.z * s, a.w * s);
}

// ---------------------------------------------------------------------------
// Kernel 1: per-pixel covariance. Block = 1024 threads = 128 quads x 8 splits.
// 2 KB contiguous per (plane,batch) access; staged 48 KB smem reduction
// (8->4->2->1) — no partial-covariance DRAM traffic. Grid = 128 blocks.
// Reads run at the measured pure-read equilibrium (~4.1 TB/s, overlapping
// prior-iteration writeback in the timed loop) — latency/pipeline floor.
// ---------------------------------------------------------------------------
__global__ __launch_bounds__(1024, 1) void k_covar(const float4* __restrict__ s4) {
    const int tid = threadIdx.x;
    const int ql  = tid & (COV_Q - 1);        // quad-local 0..127
    const int sp  = tid >> 7;                 // split 0..7 (warp-uniform)
    const int q   = blockIdx.x * COV_Q + ql;  // global quad

    float4 a0 = make_float4(0.f, 0.f, 0.f, 0.f);
    float4 a1 = a0, a2 = a0, a3 = a0, a4 = a0, a5 = a0;

#pragma unroll 2
    for (int i = 0; i < 8; ++i) {
        const int b = sp * 8 + i;
        const float4* base = s4 + (size_t)b * (3 * N_Q) + q;
        const float4 s0 = __ldcs(base);
        const float4 s1 = __ldcs(base + N_Q);
        const float4 s2 = __ldcs(base + 2 * N_Q);
        a0 = f4fma(s0, s0, a0); a1 = f4fma(s0, s1, a1); a2 = f4fma(s0, s2, a2);
        a3 = f4fma(s1, s1, a3); a4 = f4fma(s1, s2, a4); a5 = f4fma(s2, s2, a5);
    }

    // staged reduction: 8 -> 4 -> 2 -> 1 splits, 48 KB smem
    __shared__ float4 sh[4][6][COV_Q];

    if (sp >= 4) {
        sh[sp - 4][0][ql] = a0; sh[sp - 4][1][ql] = a1; sh[sp - 4][2][ql] = a2;
        sh[sp - 4][3][ql] = a3; sh[sp - 4][4][ql] = a4; sh[sp - 4][5][ql] = a5;
    }
    __syncthreads();
    if (sp < 4) {
        a0 = f4add(a0, sh[sp][0][ql]); a1 = f4add(a1, sh[sp][1][ql]);
        a2 = f4add(a2, sh[sp][2][ql]); a3 = f4add(a3, sh[sp][3][ql]);
        a4 = f4add(a4, sh[sp][4][ql]); a5 = f4add(a5, sh[sp][5][ql]);
    }
    __syncthreads();
    if (sp == 2 || sp == 3) {
        sh[sp - 2][0][ql] = a0; sh[sp - 2][1][ql] = a1; sh[sp - 2][2][ql] = a2;
        sh[sp - 2][3][ql] = a3; sh[sp - 2][4][ql] = a4; sh[sp - 2][5][ql] = a5;
    }
    __syncthreads();
    if (sp < 2) {
        a0 = f4add(a0, sh[sp][0][ql]); a1 = f4add(a1, sh[sp][1][ql]);
        a2 = f4add(a2, sh[sp][2][ql]); a3 = f4add(a3, sh[sp][3][ql]);
        a4 = f4add(a4, sh[sp][4][ql]); a5 = f4add(a5, sh[sp][5][ql]);
    }
    __syncthreads();
    if (sp == 1) {
        sh[0][0][ql] = a0; sh[0][1][ql] = a1; sh[0][2][ql] = a2;
        sh[0][3][ql] = a3; sh[0][4][ql] = a4; sh[0][5][ql] = a5;
    }
    __syncthreads();

    float tr = 0.f;
    if (sp == 0) {
        const float ib = 1.0f / 64.0f;
        a0 = f4scale(f4add(a0, sh[0][0][ql]), ib);
        a1 = f4scale(f4add(a1, sh[0][1][ql]), ib);
        a2 = f4scale(f4add(a2, sh[0][2][ql]), ib);
        a3 = f4scale(f4add(a3, sh[0][3][ql]), ib);
        a4 = f4scale(f4add(a4, sh[0][4][ql]), ib);
        a5 = f4scale(f4add(a5, sh[0][5][ql]), ib);

        float4* g4 = (float4*)g_G;
        g4[0 * N_Q + q] = a0; g4[1 * N_Q + q] = a1; g4[2 * N_Q + q] = a2;
        g4[3 * N_Q + q] = a3; g4[4 * N_Q + q] = a4; g4[5 * N_Q + q] = a5;

        const float4 td = f4add(f4add(a0, a3), a5);
        tr = td.x + td.y + td.z + td.w;
#pragma unroll
        for (int o = 16; o > 0; o >>= 1)
            tr += __shfl_down_sync(0xffffffffu, tr, o);
    }

    __shared__ float shr[4];
    if (sp == 0 && (tid & 31) == 0) shr[tid >> 5] = tr;
    __syncthreads();
    if (tid == 0)
        g_partial[blockIdx.x] = shr[0] + shr[1] + shr[2] + shr[3];
}

// ---------------------------------------------------------------------------
// Kernel 2: per-pixel matrix prep (fp32).
//   G = alpha*G/norm + (1-alpha)*0.25*I
//   A = 8*L*Ginv ; 8L ; d = sqrt(1.28)*rowsum(L)
//   (C = 0.64*G*Ginv == 0.64*I at fp32 rounding — folded into k_apply.)
// ---------------------------------------------------------------------------
__global__ __launch_bounds__(256) void k_prep(const float* __restrict__ t) {
    // reduce 128 trace partials redundantly per block
    __shared__ float sh_sum;
    {
        float v = (threadIdx.x < NBLK_COV) ? g_partial[threadIdx.x] : 0.f;
#pragma unroll
        for (int o = 16; o > 0; o >>= 1)
            v += __shfl_down_sync(0xffffffffu, v, o);
        __shared__ float sh[8];
        const int lane = threadIdx.x & 31;
        const int w    = threadIdx.x >> 5;
        if (lane == 0) sh[w] = v;
        __syncthreads();
        if (threadIdx.x == 0) {
            float acc = 0.f;
#pragma unroll
            for (int i = 0; i < 8; ++i) acc += sh[i];
            sh_sum = acc;
        }
        __syncthreads();
    }

    const int p = blockIdx.x * blockDim.x + threadIdx.x;
    const float t0 = __ldg(t);
    const float diag_mean = sh_sum / (65536.0f * 3.0f);
    const float norm  = (t0 == 1.0f) ? diag_mean * 4.0f : 1.0f;
    const float alpha = 0.5f * __expf(-4.5f * (1.0f - t0));
    const float sa = alpha / norm;
    const float diag_add = (1.0f - alpha) * 0.25f;

    const float a00 = g_G[0 * N_PIX + p] * sa + diag_add;
    const float a01 = g_G[1 * N_PIX + p] * sa;
    const float a02 = g_G[2 * N_PIX + p] * sa;
    const float a11 = g_G[3 * N_PIX + p] * sa + diag_add;
    const float a12 = g_G[4 * N_PIX + p] * sa;
    const float a22 = g_G[5 * N_PIX + p] * sa + diag_add;

    // adjugate inverse (fp32)
    const float c00 = a11 * a22 - a12 * a12;
    const float c01 = a02 * a12 - a01 * a22;
    const float c02 = a01 * a12 - a02 * a11;
    const float det = a00 * c00 + a01 * c01 + a02 * c02;
    const float id  = 1.0f / det;
    const float i00 = c00 * id;
    const float i01 = c01 * id;
    const float i02 = c02 * id;
    const float i11 = (a00 * a22 - a02 * a02) * id;
    const float i12 = (a01 * a02 - a00 * a12) * id;
    const float i22 = (a00 * a11 - a01 * a01) * id;

    // Cholesky (fp32)
    const float l00 = sqrtf(a00);
    const float il00 = 1.0f / l00;
    const float l10 = a01 * il00;
    const float l20 = a02 * il00;
    const float l11 = sqrtf(a11 - l10 * l10);
    const float l21 = (a12 - l20 * l10) / l11;
    const float l22 = sqrtf(a22 - l20 * l20 - l21 * l21);

    // A = 8 * L * Ginv
    const float A00 = 8.0f * (l00 * i00);
    const float A01 = 8.0f * (l00 * i01);
    const float A02 = 8.0f * (l00 * i02);
    const float A10 = 8.0f * (l10 * i00 + l11 * i01);
    const float A11 = 8.0f * (l10 * i01 + l11 * i11);
    const float A12 = 8.0f * (l10 * i02 + l11 * i12);
    const float A20 = 8.0f * (l20 * i00 + l21 * i01 + l22 * i02);
    const float A21 = 8.0f * (l20 * i01 + l21 * i11 + l22 * i12);
    const float A22 = 8.0f * (l20 * i02 + l21 * i12 + l22 * i22);

    const float bg = 1.1313708498984762f;  // sqrt(2*8*0.08)

    float* m = g_mats;
    m[ 0 * N_PIX + p] = A00; m[ 1 * N_PIX + p] = A01; m[ 2 * N_PIX + p] = A02;
    m[ 3 * N_PIX + p] = A10; m[ 4 * N_PIX + p] = A11; m[ 5 * N_PIX + p] = A12;
    m[ 6 * N_PIX + p] = A20; m[ 7 * N_PIX + p] = A21; m[ 8 * N_PIX + p] = A22;
    m[ 9 * N_PIX + p] = 8.0f * l00;
    m[10 * N_PIX + p] = 8.0f * l10;
    m[11 * N_PIX + p] = 8.0f * l11;
    m[12 * N_PIX + p] = 8.0f * l20;
    m[13 * N_PIX + p] = 8.0f * l21;
    m[14 * N_PIX + p] = 8.0f * l22;
    m[15 * N_PIX + p] = bg * l00;
    m[16 * N_PIX + p] = bg * (l10 + l11);
    m[17 * N_PIX + p] = bg * (l20 + l21 + l22);
}

// ---------------------------------------------------------------------------
// Kernel 3: streaming apply, float4 pixel-quads, 4 batches per thread.
//   drift_x = A r ; drift_r = -(8L) x - 0.64 r ; diffusion = [0, d]
// At the measured mixed read/write DRAM ceiling (~6.5 TB/s effective).
// ---------------------------------------------------------------------------
__global__ __launch_bounds__(256) void k_apply(const float4* __restrict__ u4,
                                               float4* __restrict__ out4) {
    const int idx = blockIdx.x * blockDim.x + threadIdx.x;  // 0..262143
    const int q   = idx & (N_Q - 1);
    const int bq  = idx >> 14;  // 0..15

    const float4* m4 = (const float4*)g_mats;
    const float4 A00 = __ldg(m4 +  0 * N_Q + q), A01 = __ldg(m4 +  1 * N_Q + q), A02 = __ldg(m4 +  2 * N_Q + q);
    const float4 A10 = __ldg(m4 +  3 * N_Q + q), A11 = __ldg(m4 +  4 * N_Q + q), A12 = __ldg(m4 +  5 * N_Q + q);
    const float4 A20 = __ldg(m4 +  6 * N_Q + q), A21 = __ldg(m4 +  7 * N_Q + q), A22 = __ldg(m4 +  8 * N_Q + q);
    const float4 L00 = __ldg(m4 +  9 * N_Q + q);
    const float4 L10 = __ldg(m4 + 10 * N_Q + q), L11 = __ldg(m4 + 11 * N_Q + q);
    const float4 L20 = __ldg(m4 + 12 * N_Q + q), L21 = __ldg(m4 + 13 * N_Q + q), L22 = __ldg(m4 + 14 * N_Q + q);
    const float4 D0  = __ldg(m4 + 15 * N_Q + q), D1 = __ldg(m4 + 16 * N_Q + q), D2 = __ldg(m4 + 17 * N_Q + q);

    const size_t diff_off = (size_t)BATCH * 6 * N_Q;  // 6291456 float4
    const float4 zero = make_float4(0.f, 0.f, 0.f, 0.f);
    const float cg = 0.64f;  // 0.64 * G * Ginv == 0.64 * I (fp32 rounding level)

#pragma unroll
    for (int i = 0; i < 4; ++i) {
        const int b = bq * 4 + i;
        const float4* ub = u4 + (size_t)b * (6 * N_Q) + q;
        const float4 x0 = __ldcs(ub);
        const float4 x1 = __ldcs(ub + N_Q);
        const float4 x2 = __ldcs(ub + 2 * N_Q);
        const float4 r0 = __ldcs(ub + 3 * N_Q);
        const float4 r1 = __ldcs(ub + 4 * N_Q);
        const float4 r2 = __ldcs(ub + 5 * N_Q);

        // drift_x = A r
        const float4 dx0 = f4fma(A02, r2, f4fma(A01, r1, f4mul(A00, r0)));
        const float4 dx1 = f4fma(A12, r2, f4fma(A11, r1, f4mul(A10, r0)));
        const float4 dx2 = f4fma(A22, r2, f4fma(A21, r1, f4mul(A20, r0)));
        // drift_r = -( (8L) x + 0.64 r )
        const float4 dr0 = f4neg(f4fma(L00, x0, f4scale(r0, cg)));
        const float4 dr1 = f4neg(f4fma(L11, x1, f4fma(L10, x0, f4scale(r1, cg))));
        const float4 dr2 = f4neg(f4fma(L22, x2, f4fma(L21, x1, f4fma(L20, x0, f4scale(r2, cg)))));

        float4* ob = out4 + (size_t)b * (6 * N_Q) + q;
        __stcs(ob + 0 * N_Q, dx0);
        __stcs(ob + 1 * N_Q, dx1);
        __stcs(ob + 2 * N_Q, dx2);
        __stcs(ob + 3 * N_Q, dr0);
        __stcs(ob + 4 * N_Q, dr1);
        __stcs(ob + 5 * N_Q, dr2);

        float4* db = ob + diff_off;
        __stcs(db + 0 * N_Q, zero);
        __stcs(db + 1 * N_Q, zero);
        __stcs(db + 2 * N_Q, zero);
        __stcs(db + 3 * N_Q, D0);
        __stcs(db + 4 * N_Q, D1);
        __stcs(db + 5 * N_Q, D2);
    }
}

// ---------------------------------------------------------------------------
extern "C" void kernel_launch(void* const* d_in, const int* in_sizes, int n_in,
                              void* d_out, int out_size) {
    const float4* u4 = (const float4*)d_in[0];   // [64, 6, 256, 256]
    const float4* s4 = (const float4*)d_in[1];   // [64, 3, 256, 256]
    const float*  t  = (const float*)d_in[2];    // [64]
    float4* out4 = (float4*)d_out;               // drift + diffusion

    k_covar<<<NBLK_COV, 1024>>>(s4);
    k_prep<<<N_PIX / 256, 256>>>(t);
    k_apply<<<(N_Q * 16) / 256, 256>>>(u4, out4);
}